// round 1
// baseline (speedup 1.0000x reference)
#include <cuda_runtime.h>
#include <cuda_bf16.h>
#include <math.h>

// Problem constants
#define TOK   8192            // B*S = 4*2048
#define E     1024
#define H3    3072            // 3*E
#define MLPD  4096
#define NHEAD 16
#define HDIM  64
#define SEQ   2048

// ---------------------------------------------------------------------------
// Scratch (device globals; allocations are forbidden)
// ---------------------------------------------------------------------------
__device__ float g_h   [(size_t)TOK * E];     // layernorm output (reused)
__device__ float g_qkv [(size_t)TOK * H3];    // qkv projection
__device__ float g_attn[(size_t)TOK * E];     // attention output
__device__ float g_x1  [(size_t)TOK * E];     // residual after attn sublayer
__device__ float g_mlp [(size_t)TOK * MLPD];  // gelu(h@w1^T+b1)

// ---------------------------------------------------------------------------
// LayerNorm: one block per row of 1024, 256 threads, float4 everywhere
// ---------------------------------------------------------------------------
__global__ void ln_kernel(const float* __restrict__ x,
                          const float* __restrict__ g,
                          const float* __restrict__ b,
                          float* __restrict__ y)
{
    int row = blockIdx.x;
    int tid = threadIdx.x;                       // 0..255, 256*4 = 1024
    const float4* xr = (const float4*)(x + (size_t)row * E);
    float4 v = xr[tid];

    float s  = v.x + v.y + v.z + v.w;
    float ss = v.x * v.x + v.y * v.y + v.z * v.z + v.w * v.w;

    __shared__ float sbuf[32], sbuf2[32];
    #pragma unroll
    for (int o = 16; o > 0; o >>= 1) {
        s  += __shfl_down_sync(0xffffffffu, s,  o);
        ss += __shfl_down_sync(0xffffffffu, ss, o);
    }
    int warp = tid >> 5, lane = tid & 31;
    if (lane == 0) { sbuf[warp] = s; sbuf2[warp] = ss; }
    __syncthreads();
    if (warp == 0) {
        s  = lane < 8 ? sbuf[lane]  : 0.f;
        ss = lane < 8 ? sbuf2[lane] : 0.f;
        #pragma unroll
        for (int o = 4; o > 0; o >>= 1) {
            s  += __shfl_down_sync(0xffffffffu, s,  o);
            ss += __shfl_down_sync(0xffffffffu, ss, o);
        }
        if (lane == 0) { sbuf[0] = s; sbuf2[0] = ss; }
    }
    __syncthreads();
    float mean = sbuf[0] * (1.0f / E);
    float var  = sbuf2[0] * (1.0f / E) - mean * mean;
    float rstd = rsqrtf(var + 1e-5f);

    float4 gv = ((const float4*)g)[tid];
    float4 bv = ((const float4*)b)[tid];
    float4 o;
    o.x = (v.x - mean) * rstd * gv.x + bv.x;
    o.y = (v.y - mean) * rstd * gv.y + bv.y;
    o.z = (v.z - mean) * rstd * gv.z + bv.z;
    o.w = (v.w - mean) * rstd * gv.w + bv.w;
    ((float4*)(y + (size_t)row * E))[tid] = o;
}

// ---------------------------------------------------------------------------
// NT GEMM: C[M,N] = act(A[M,K] * B[N,K]^T + bias) + residual
// Both A and B row-major with K contiguous (true for every matmul here).
// 128x128 tile, BK=16, 256 threads, 8x8 per-thread micro-tile.
// act: 0 = none, 1 = exact GELU
// ---------------------------------------------------------------------------
#define BM 128
#define BN 128
#define BK 16
#define TM 8
#define TN 8

__global__ __launch_bounds__(256, 2)
void gemm_nt(const float* __restrict__ A, const float* __restrict__ B,
             const float* __restrict__ bias, const float* __restrict__ res,
             float* __restrict__ C, int M, int N, int K, int act)
{
    __shared__ float As[BK][BM];
    __shared__ float Bs[BK][BN];

    int bn = blockIdx.x, bm = blockIdx.y;
    int tid = threadIdx.x;            // 0..255
    int tx = tid & 15;                // 16 columns of threads
    int ty = tid >> 4;                // 16 rows of threads

    const float* Ab = A + (size_t)bm * BM * K;
    const float* Bb = B + (size_t)bn * BN * K;

    float acc[TM][TN];
    #pragma unroll
    for (int i = 0; i < TM; i++)
        #pragma unroll
        for (int j = 0; j < TN; j++) acc[i][j] = 0.f;

    for (int k0 = 0; k0 < K; k0 += BK) {
        // load A tile: 128 rows x 16 k = 512 float4, 2 per thread
        #pragma unroll
        for (int i = 0; i < 2; i++) {
            int idx = tid * 2 + i;            // 0..511
            int row = idx >> 2;               // 0..127
            int c4  = idx & 3;                // which float4 within 16 k
            float4 v = *(const float4*)(Ab + (size_t)row * K + k0 + c4 * 4);
            As[c4 * 4 + 0][row] = v.x;
            As[c4 * 4 + 1][row] = v.y;
            As[c4 * 4 + 2][row] = v.z;
            As[c4 * 4 + 3][row] = v.w;
        }
        #pragma unroll
        for (int i = 0; i < 2; i++) {
            int idx = tid * 2 + i;
            int row = idx >> 2;
            int c4  = idx & 3;
            float4 v = *(const float4*)(Bb + (size_t)row * K + k0 + c4 * 4);
            Bs[c4 * 4 + 0][row] = v.x;
            Bs[c4 * 4 + 1][row] = v.y;
            Bs[c4 * 4 + 2][row] = v.z;
            Bs[c4 * 4 + 3][row] = v.w;
        }
        __syncthreads();

        #pragma unroll
        for (int k = 0; k < BK; k++) {
            float ra[TM], rb[TN];
            float4 a0 = *(const float4*)&As[k][ty * TM];
            float4 a1 = *(const float4*)&As[k][ty * TM + 4];
            float4 b0 = *(const float4*)&Bs[k][tx * TN];
            float4 b1 = *(const float4*)&Bs[k][tx * TN + 4];
            ra[0]=a0.x; ra[1]=a0.y; ra[2]=a0.z; ra[3]=a0.w;
            ra[4]=a1.x; ra[5]=a1.y; ra[6]=a1.z; ra[7]=a1.w;
            rb[0]=b0.x; rb[1]=b0.y; rb[2]=b0.z; rb[3]=b0.w;
            rb[4]=b1.x; rb[5]=b1.y; rb[6]=b1.z; rb[7]=b1.w;
            #pragma unroll
            for (int i = 0; i < TM; i++)
                #pragma unroll
                for (int j = 0; j < TN; j++)
                    acc[i][j] += ra[i] * rb[j];
        }
        __syncthreads();
    }

    // epilogue
    #pragma unroll
    for (int i = 0; i < TM; i++) {
        int row = bm * BM + ty * TM + i;
        #pragma unroll
        for (int j = 0; j < TN; j++) {
            int col = bn * BN + tx * TN + j;
            float v = acc[i][j];
            if (bias) v += bias[col];
            if (act == 1) v = 0.5f * v * (1.0f + erff(v * 0.70710678118654752f));
            if (res) v += res[(size_t)row * N + col];
            C[(size_t)row * N + col] = v;
        }
    }
}

// ---------------------------------------------------------------------------
// Flash attention: grid (qtile=32, head=16, batch=4), 128 threads.
// Q tile 64 rows, KV tiles of 32 rows, online softmax.
// Each thread: one (row, half) pair; owns 32 of 64 head dims.
// qkv layout: [token, 3*E] with q at +h*64, k at +1024+h*64, v at +2048+h*64.
// ---------------------------------------------------------------------------
__global__ __launch_bounds__(128)
void attn_kernel(const float* __restrict__ qkv, float* __restrict__ out)
{
    __shared__ float Qs[64][65];
    __shared__ float Ks[32][65];
    __shared__ float Vs[32][65];
    __shared__ float Ss[64][33];

    int qt = blockIdx.x, h = blockIdx.y, b = blockIdx.z;
    int tid = threadIdx.x;
    int row  = tid >> 1;      // 0..63
    int half = tid & 1;       // 0 or 1 (owns d in [half*32, half*32+32))

    // load Q tile: 64 rows x 64 d = 1024 float4
    for (int i = tid; i < 64 * 16; i += 128) {
        int r = i >> 4, c4 = i & 15;
        size_t base = (size_t)(b * SEQ + qt * 64 + r) * H3 + h * HDIM + c4 * 4;
        float4 v = *(const float4*)(qkv + base);
        Qs[r][c4 * 4 + 0] = v.x;
        Qs[r][c4 * 4 + 1] = v.y;
        Qs[r][c4 * 4 + 2] = v.z;
        Qs[r][c4 * 4 + 3] = v.w;
    }

    float acc[32];
    #pragma unroll
    for (int i = 0; i < 32; i++) acc[i] = 0.f;
    float m_i = -1e30f, l_i = 0.f;

    __syncthreads();

    for (int kt = 0; kt < SEQ / 32; kt++) {
        // load K and V tiles (32 rows x 64 d each = 512 float4 each)
        for (int i = tid; i < 32 * 16; i += 128) {
            int r = i >> 4, c4 = i & 15;
            size_t base = (size_t)(b * SEQ + kt * 32 + r) * H3 + h * HDIM + c4 * 4;
            float4 kv = *(const float4*)(qkv + base + E);
            Ks[r][c4 * 4 + 0] = kv.x;
            Ks[r][c4 * 4 + 1] = kv.y;
            Ks[r][c4 * 4 + 2] = kv.z;
            Ks[r][c4 * 4 + 3] = kv.w;
            float4 vv = *(const float4*)(qkv + base + 2 * E);
            Vs[r][c4 * 4 + 0] = vv.x;
            Vs[r][c4 * 4 + 1] = vv.y;
            Vs[r][c4 * 4 + 2] = vv.z;
            Vs[r][c4 * 4 + 3] = vv.w;
        }
        __syncthreads();

        // scores: this thread computes 16 of the row's 32 scores
        #pragma unroll
        for (int jj = 0; jj < 16; jj++) {
            int j = half * 16 + jj;
            float s = 0.f;
            #pragma unroll
            for (int k = 0; k < HDIM; k++) s += Qs[row][k] * Ks[j][k];
            Ss[row][j] = s * 0.125f;       // 1/sqrt(64)
        }
        __syncthreads();

        // online softmax update over the 32 keys of this tile
        float mx = m_i;
        #pragma unroll
        for (int j = 0; j < 32; j++) mx = fmaxf(mx, Ss[row][j]);
        float alpha = __expf(m_i - mx);
        #pragma unroll
        for (int dd = 0; dd < 32; dd++) acc[dd] *= alpha;
        l_i *= alpha;
        for (int j = 0; j < 32; j++) {
            float p = __expf(Ss[row][j] - mx);
            l_i += p;
            #pragma unroll
            for (int dd = 0; dd < 32; dd++)
                acc[dd] += p * Vs[j][half * 32 + dd];
        }
        m_i = mx;
        __syncthreads();
    }

    // write out: [token, h*64 + d]
    float inv = 1.0f / l_i;
    size_t t = (size_t)(b * SEQ + qt * 64 + row);
    float* op = out + t * E + h * HDIM + half * 32;
    #pragma unroll
    for (int dd = 0; dd < 32; dd++) op[dd] = acc[dd] * inv;
}

// ---------------------------------------------------------------------------
// Launch
// ---------------------------------------------------------------------------
extern "C" void kernel_launch(void* const* d_in, const int* in_sizes, int n_in,
                              void* d_out, int out_size)
{
    const float* x     = (const float*)d_in[0];
    const float* qkv_w = (const float*)d_in[1];
    const float* fc_w  = (const float*)d_in[2];
    const float* fc_b  = (const float*)d_in[3];
    const float* ln1_g = (const float*)d_in[4];
    const float* ln1_b = (const float*)d_in[5];
    const float* ln2_g = (const float*)d_in[6];
    const float* ln2_b = (const float*)d_in[7];
    const float* w1    = (const float*)d_in[8];
    const float* b1    = (const float*)d_in[9];
    const float* w2    = (const float*)d_in[10];
    const float* b2    = (const float*)d_in[11];
    float* out = (float*)d_out;

    float *ph, *pqkv, *pattn, *px1, *pmlp;
    cudaGetSymbolAddress((void**)&ph,    g_h);
    cudaGetSymbolAddress((void**)&pqkv,  g_qkv);
    cudaGetSymbolAddress((void**)&pattn, g_attn);
    cudaGetSymbolAddress((void**)&px1,   g_x1);
    cudaGetSymbolAddress((void**)&pmlp,  g_mlp);

    // 1. h = LN1(x)
    ln_kernel<<<TOK, 256>>>(x, ln1_g, ln1_b, ph);
    // 2. qkv = h @ qkv_w^T
    gemm_nt<<<dim3(H3 / BN, TOK / BM), 256>>>(ph, qkv_w, nullptr, nullptr,
                                              pqkv, TOK, H3, E, 0);
    // 3. attention
    attn_kernel<<<dim3(SEQ / 64, NHEAD, 4), 128>>>(pqkv, pattn);
    // 4. x1 = x + attn @ fc_w^T + fc_b
    gemm_nt<<<dim3(E / BN, TOK / BM), 256>>>(pattn, fc_w, fc_b, x,
                                             px1, TOK, E, E, 0);
    // 5. h = LN2(x1)
    ln_kernel<<<TOK, 256>>>(px1, ln2_g, ln2_b, ph);
    // 6. mlp = gelu(h @ w1^T + b1)
    gemm_nt<<<dim3(MLPD / BN, TOK / BM), 256>>>(ph, w1, b1, nullptr,
                                                pmlp, TOK, MLPD, E, 1);
    // 7. out = x1 + mlp @ w2^T + b2
    gemm_nt<<<dim3(E / BN, TOK / BM), 256>>>(pmlp, w2, b2, px1,
                                             out, TOK, E, MLPD, 0);
}

// round 3
// speedup vs baseline: 1.1183x; 1.1183x over previous
#include <cuda_runtime.h>
#include <cuda_bf16.h>
#include <cstdint>
#include <math.h>

#define TOK   8192
#define E     1024
#define H3    3072
#define MLPD  4096
#define NHEAD 16
#define HDIM  64
#define SEQ   2048

// ---------------------------------------------------------------------------
// Scratch
// ---------------------------------------------------------------------------
__device__ float g_h   [(size_t)TOK * E];
__device__ float g_qkv [(size_t)TOK * H3];
__device__ float g_attn[(size_t)TOK * E];
__device__ float g_x1  [(size_t)TOK * E];
__device__ float g_mlp [(size_t)TOK * MLPD];

__device__ __forceinline__ uint32_t smem_u32(const void* p) {
    uint32_t a;
    asm("{ .reg .u64 t; cvta.to.shared.u64 t, %1; cvt.u32.u64 %0, t; }"
        : "=r"(a) : "l"(p));
    return a;
}

#define LDSM_X4(r, addr) \
    asm volatile("ldmatrix.sync.aligned.m8n8.x4.shared.b16 {%0,%1,%2,%3}, [%4];" \
        : "=r"((r)[0]), "=r"((r)[1]), "=r"((r)[2]), "=r"((r)[3]) : "r"(addr))

__device__ __forceinline__ void mma_bf16(float* c, const uint32_t* a, const uint32_t* b) {
    asm volatile(
        "mma.sync.aligned.m16n8k16.row.col.f32.bf16.bf16.f32 "
        "{%0,%1,%2,%3}, {%4,%5,%6,%7}, {%8,%9}, {%0,%1,%2,%3};"
        : "+f"(c[0]), "+f"(c[1]), "+f"(c[2]), "+f"(c[3])
        : "r"(a[0]), "r"(a[1]), "r"(a[2]), "r"(a[3]), "r"(b[0]), "r"(b[1]));
}

// ---------------------------------------------------------------------------
// LayerNorm
// ---------------------------------------------------------------------------
__global__ void ln_kernel(const float* __restrict__ x,
                          const float* __restrict__ g,
                          const float* __restrict__ b,
                          float* __restrict__ y)
{
    int row = blockIdx.x;
    int tid = threadIdx.x;
    const float4* xr = (const float4*)(x + (size_t)row * E);
    float4 v = xr[tid];

    float s  = v.x + v.y + v.z + v.w;
    float ss = v.x * v.x + v.y * v.y + v.z * v.z + v.w * v.w;

    __shared__ float sbuf[32], sbuf2[32];
    #pragma unroll
    for (int o = 16; o > 0; o >>= 1) {
        s  += __shfl_down_sync(0xffffffffu, s,  o);
        ss += __shfl_down_sync(0xffffffffu, ss, o);
    }
    int warp = tid >> 5, lane = tid & 31;
    if (lane == 0) { sbuf[warp] = s; sbuf2[warp] = ss; }
    __syncthreads();
    if (warp == 0) {
        s  = lane < 8 ? sbuf[lane]  : 0.f;
        ss = lane < 8 ? sbuf2[lane] : 0.f;
        #pragma unroll
        for (int o = 4; o > 0; o >>= 1) {
            s  += __shfl_down_sync(0xffffffffu, s,  o);
            ss += __shfl_down_sync(0xffffffffu, ss, o);
        }
        if (lane == 0) { sbuf[0] = s; sbuf2[0] = ss; }
    }
    __syncthreads();
    float mean = sbuf[0] * (1.0f / E);
    float var  = sbuf2[0] * (1.0f / E) - mean * mean;
    float rstd = rsqrtf(var + 1e-5f);

    float4 gv = ((const float4*)g)[tid];
    float4 bv = ((const float4*)b)[tid];
    float4 o;
    o.x = (v.x - mean) * rstd * gv.x + bv.x;
    o.y = (v.y - mean) * rstd * gv.y + bv.y;
    o.z = (v.z - mean) * rstd * gv.z + bv.z;
    o.w = (v.w - mean) * rstd * gv.w + bv.w;
    ((float4*)(y + (size_t)row * E))[tid] = o;
}

// ---------------------------------------------------------------------------
// Split-bf16 mma.sync NT GEMM: C[M,N] = act(A[M,K] @ B[N,K]^T + bias) + res
// CTA 128x128, BK=32 fp32. 8 warps, each 64(m) x 32(n).
// smem stage (40960 B): Ah(10240) Al(10240) Bh(10240) Bl(10240),
// each matrix 128 rows x 32 bf16, padded row stride 40 elems (80 B).
// Double buffered (2 stages = 81920 B dynamic smem).
// ---------------------------------------------------------------------------
#define SROW   80          // padded row stride in bytes (40 bf16)
#define MATB   10240       // bytes per matrix (128 * 80)
#define STAGEB 40960
#define GEMM_SMEM (2 * STAGEB)

struct StageRegs { float4 a[4]; float4 b[4]; };

__device__ __forceinline__ void ldg_stage(StageRegs& s,
                                          const float* __restrict__ Ab,
                                          const float* __restrict__ Bb,
                                          int K, int k0, int tid)
{
    #pragma unroll
    for (int i = 0; i < 4; i++) {
        int idx = i * 256 + tid;
        int r = idx >> 3, c4 = idx & 7;
        s.a[i] = *(const float4*)(Ab + (size_t)r * K + k0 + c4 * 4);
        s.b[i] = *(const float4*)(Bb + (size_t)r * K + k0 + c4 * 4);
    }
}

__device__ __forceinline__ void cvt_sts(float4 v, char* hi, char* lo, uint32_t off)
{
    uint32_t x0 = __float_as_uint(v.x), x1 = __float_as_uint(v.y);
    uint32_t x2 = __float_as_uint(v.z), x3 = __float_as_uint(v.w);
    uint32_t h01 = (x1 & 0xffff0000u) | (x0 >> 16);
    uint32_t h23 = (x3 & 0xffff0000u) | (x2 >> 16);
    float l0 = v.x - __uint_as_float(x0 & 0xffff0000u);
    float l1 = v.y - __uint_as_float(x1 & 0xffff0000u);
    float l2 = v.z - __uint_as_float(x2 & 0xffff0000u);
    float l3 = v.w - __uint_as_float(x3 & 0xffff0000u);
    uint32_t l01, l23;
    asm("cvt.rn.bf16x2.f32 %0, %1, %2;" : "=r"(l01) : "f"(l1), "f"(l0));
    asm("cvt.rn.bf16x2.f32 %0, %1, %2;" : "=r"(l23) : "f"(l3), "f"(l2));
    *(uint2*)(hi + off) = make_uint2(h01, h23);
    *(uint2*)(lo + off) = make_uint2(l01, l23);
}

__device__ __forceinline__ void sts_stage(const StageRegs& s, char* stg, int tid)
{
    #pragma unroll
    for (int i = 0; i < 4; i++) {
        int idx = i * 256 + tid;
        int r = idx >> 3, c4 = idx & 7;
        uint32_t off = (uint32_t)(r * SROW + c4 * 8);
        cvt_sts(s.a[i], stg,            stg + MATB,     off);
        cvt_sts(s.b[i], stg + 2 * MATB, stg + 3 * MATB, off);
    }
}

__global__ __launch_bounds__(256, 1)
void gemm_mma(const float* __restrict__ A, const float* __restrict__ B,
              const float* __restrict__ bias, const float* __restrict__ res,
              float* __restrict__ C, int M, int N, int K, int act)
{
    extern __shared__ char sm[];
    uint32_t sb = smem_u32(sm);
    int tid = threadIdx.x, w = tid >> 5, lane = tid & 31;
    int wm = w >> 2, wn = w & 3;         // warp tile: rows wm*64, cols wn*32
    int bn = blockIdx.x, bm = blockIdx.y;

    const float* Ab = A + (size_t)bm * 128 * K;
    const float* Bb = B + (size_t)bn * 128 * K;
    int nch = K >> 5;

    float acc[4][4][4];
    #pragma unroll
    for (int i = 0; i < 4; i++)
        #pragma unroll
        for (int j = 0; j < 4; j++)
            #pragma unroll
            for (int c = 0; c < 4; c++) acc[i][j][c] = 0.f;

    StageRegs st;
    ldg_stage(st, Ab, Bb, K, 0, tid);
    sts_stage(st, sm, tid);
    __syncthreads();

    // precomputed ldmatrix lane address components
    uint32_t a_row = (uint32_t)(wm * 64 + (lane & 15)) * SROW + ((lane >> 4) * 8) * 2;
    uint32_t b_row = (uint32_t)(wn * 32 + (lane & 7) + ((lane >> 4) & 1) * 8) * SROW
                   + (((lane >> 3) & 1) * 8) * 2;

    for (int k = 0; k < nch; k++) {
        StageRegs nxt;
        if (k + 1 < nch) ldg_stage(nxt, Ab, Bb, K, (k + 1) * 32, tid);

        uint32_t stg = sb + (uint32_t)(k & 1) * STAGEB;
        #pragma unroll
        for (int ks = 0; ks < 2; ks++) {
            uint32_t koff = (uint32_t)(ks * 32);  // 16 elems * 2 B
            uint32_t ah[4][4], al[4][4], bh[2][4], bl[2][4];
            #pragma unroll
            for (int mf = 0; mf < 4; mf++) {
                uint32_t addr = stg + a_row + (uint32_t)(mf * 16) * SROW + koff;
                LDSM_X4(ah[mf], addr);
                LDSM_X4(al[mf], addr + MATB);
            }
            #pragma unroll
            for (int np = 0; np < 2; np++) {
                uint32_t addr = stg + 2 * MATB + b_row + (uint32_t)(np * 16) * SROW + koff;
                LDSM_X4(bh[np], addr);
                LDSM_X4(bl[np], addr + MATB);
            }
            #pragma unroll
            for (int mf = 0; mf < 4; mf++)
                #pragma unroll
                for (int nf = 0; nf < 4; nf++) {
                    const uint32_t* bhf = &bh[nf >> 1][(nf & 1) * 2];
                    const uint32_t* blf = &bl[nf >> 1][(nf & 1) * 2];
                    mma_bf16(acc[mf][nf], ah[mf], bhf);
                    mma_bf16(acc[mf][nf], ah[mf], blf);
                    mma_bf16(acc[mf][nf], al[mf], bhf);
                }
        }
        __syncthreads();
        if (k + 1 < nch) {
            sts_stage(nxt, sm + ((k + 1) & 1) * STAGEB, tid);
            __syncthreads();
        }
    }

    // epilogue
    int g = lane >> 2, tig = lane & 3;
    #pragma unroll
    for (int mf = 0; mf < 4; mf++) {
        #pragma unroll
        for (int h2 = 0; h2 < 2; h2++) {
            int row = bm * 128 + wm * 64 + mf * 16 + g + h2 * 8;
            float* Crow = C + (size_t)row * N;
            const float* Rrow = res ? res + (size_t)row * N : (const float*)0;
            #pragma unroll
            for (int nf = 0; nf < 4; nf++) {
                int col = bn * 128 + wn * 32 + nf * 8 + tig * 2;
                float v0 = acc[mf][nf][h2 * 2 + 0];
                float v1 = acc[mf][nf][h2 * 2 + 1];
                if (bias) {
                    float2 bv = *(const float2*)(bias + col);
                    v0 += bv.x; v1 += bv.y;
                }
                if (act == 1) {
                    v0 = 0.5f * v0 * (1.0f + erff(v0 * 0.70710678118654752f));
                    v1 = 0.5f * v1 * (1.0f + erff(v1 * 0.70710678118654752f));
                }
                if (Rrow) {
                    float2 rv = *(const float2*)(Rrow + col);
                    v0 += rv.x; v1 += rv.y;
                }
                *(float2*)(Crow + col) = make_float2(v0, v1);
            }
        }
    }
}

// ---------------------------------------------------------------------------
// Flash attention, Q in registers, float4 smem reads
// ---------------------------------------------------------------------------
__global__ __launch_bounds__(128)
void attn_kernel(const float* __restrict__ qkv, float* __restrict__ out)
{
    __shared__ float Ks[32][68];
    __shared__ float Vs[32][68];

    int qt = blockIdx.x, h = blockIdx.y, b = blockIdx.z;
    int tid = threadIdx.x;
    int row = tid >> 1, half = tid & 1;

    size_t t = (size_t)(b * SEQ + qt * 64 + row);
    const float* qp = qkv + t * H3 + h * HDIM;
    float q[64];
    #pragma unroll
    for (int i = 0; i < 16; i++) {
        float4 v = *(const float4*)(qp + i * 4);
        q[i * 4 + 0] = v.x * 0.125f;
        q[i * 4 + 1] = v.y * 0.125f;
        q[i * 4 + 2] = v.z * 0.125f;
        q[i * 4 + 3] = v.w * 0.125f;
    }

    float acc[32];
    #pragma unroll
    for (int i = 0; i < 32; i++) acc[i] = 0.f;
    float m_i = -1e30f, l_i = 0.f;

    for (int kt = 0; kt < SEQ / 32; kt++) {
        #pragma unroll
        for (int i = 0; i < 4; i++) {
            int idx = i * 128 + tid;
            int r = idx >> 4, c4 = idx & 15;
            size_t base = (size_t)(b * SEQ + kt * 32 + r) * H3 + h * HDIM + c4 * 4;
            float4 kv = *(const float4*)(qkv + base + E);
            Ks[r][c4 * 4 + 0] = kv.x;
            Ks[r][c4 * 4 + 1] = kv.y;
            Ks[r][c4 * 4 + 2] = kv.z;
            Ks[r][c4 * 4 + 3] = kv.w;
            float4 vv = *(const float4*)(qkv + base + 2 * E);
            Vs[r][c4 * 4 + 0] = vv.x;
            Vs[r][c4 * 4 + 1] = vv.y;
            Vs[r][c4 * 4 + 2] = vv.z;
            Vs[r][c4 * 4 + 3] = vv.w;
        }
        __syncthreads();

        float s[16];
        #pragma unroll
        for (int jj = 0; jj < 16; jj++) {
            int j = half * 16 + jj;
            float a0 = 0.f, a1 = 0.f;
            #pragma unroll
            for (int c4 = 0; c4 < 16; c4 += 2) {
                float4 k0 = *(const float4*)&Ks[j][c4 * 4];
                float4 k1 = *(const float4*)&Ks[j][c4 * 4 + 4];
                a0 += q[c4*4+0]*k0.x + q[c4*4+1]*k0.y + q[c4*4+2]*k0.z + q[c4*4+3]*k0.w;
                a1 += q[c4*4+4]*k1.x + q[c4*4+5]*k1.y + q[c4*4+6]*k1.z + q[c4*4+7]*k1.w;
            }
            s[jj] = a0 + a1;
        }

        float mh = s[0];
        #pragma unroll
        for (int jj = 1; jj < 16; jj++) mh = fmaxf(mh, s[jj]);
        mh = fmaxf(mh, __shfl_xor_sync(0xffffffffu, mh, 1));
        float mx = fmaxf(m_i, mh);
        float alpha = __expf(m_i - mx);
        #pragma unroll
        for (int dd = 0; dd < 32; dd++) acc[dd] *= alpha;

        float lh = 0.f;
        #pragma unroll
        for (int jj = 0; jj < 16; jj++) {
            s[jj] = __expf(s[jj] - mx);
            lh += s[jj];
        }
        l_i = l_i * alpha + lh + __shfl_xor_sync(0xffffffffu, lh, 1);

        #pragma unroll
        for (int jj = 0; jj < 16; jj++) {
            float pa = s[jj];
            float pb = __shfl_xor_sync(0xffffffffu, s[jj], 1);
            int ja = half * 16 + jj;
            int jb = (half ^ 1) * 16 + jj;
            #pragma unroll
            for (int c = 0; c < 8; c++) {
                float4 va = *(const float4*)&Vs[ja][half * 32 + c * 4];
                float4 vb = *(const float4*)&Vs[jb][half * 32 + c * 4];
                acc[c*4+0] += pa * va.x + pb * vb.x;
                acc[c*4+1] += pa * va.y + pb * vb.y;
                acc[c*4+2] += pa * va.z + pb * vb.z;
                acc[c*4+3] += pa * va.w + pb * vb.w;
            }
        }
        m_i = mx;
        __syncthreads();
    }

    float inv = 1.0f / l_i;
    float* op = out + t * E + h * HDIM + half * 32;
    #pragma unroll
    for (int c = 0; c < 8; c++) {
        float4 o = make_float4(acc[c*4+0]*inv, acc[c*4+1]*inv,
                               acc[c*4+2]*inv, acc[c*4+3]*inv);
        *(float4*)(op + c * 4) = o;
    }
}

// ---------------------------------------------------------------------------
// Launch
// ---------------------------------------------------------------------------
extern "C" void kernel_launch(void* const* d_in, const int* in_sizes, int n_in,
                              void* d_out, int out_size)
{
    const float* x     = (const float*)d_in[0];
    const float* qkv_w = (const float*)d_in[1];
    const float* fc_w  = (const float*)d_in[2];
    const float* fc_b  = (const float*)d_in[3];
    const float* ln1_g = (const float*)d_in[4];
    const float* ln1_b = (const float*)d_in[5];
    const float* ln2_g = (const float*)d_in[6];
    const float* ln2_b = (const float*)d_in[7];
    const float* w1    = (const float*)d_in[8];
    const float* b1    = (const float*)d_in[9];
    const float* w2    = (const float*)d_in[10];
    const float* b2    = (const float*)d_in[11];
    float* out = (float*)d_out;

    float *ph, *pqkv, *pattn, *px1, *pmlp;
    cudaGetSymbolAddress((void**)&ph,    g_h);
    cudaGetSymbolAddress((void**)&pqkv,  g_qkv);
    cudaGetSymbolAddress((void**)&pattn, g_attn);
    cudaGetSymbolAddress((void**)&px1,   g_x1);
    cudaGetSymbolAddress((void**)&pmlp,  g_mlp);

    cudaFuncSetAttribute(gemm_mma, cudaFuncAttributeMaxDynamicSharedMemorySize,
                         GEMM_SMEM);

    // 1. h = LN1(x)
    ln_kernel<<<TOK, 256>>>(x, ln1_g, ln1_b, ph);
    // 2. qkv = h @ qkv_w^T
    gemm_mma<<<dim3(H3 / 128, TOK / 128), 256, GEMM_SMEM>>>(
        ph, qkv_w, nullptr, nullptr, pqkv, TOK, H3, E, 0);
    // 3. attention
    attn_kernel<<<dim3(SEQ / 64, NHEAD, 4), 128>>>(pqkv, pattn);
    // 4. x1 = x + attn @ fc_w^T + fc_b
    gemm_mma<<<dim3(E / 128, TOK / 128), 256, GEMM_SMEM>>>(
        pattn, fc_w, fc_b, x, px1, TOK, E, E, 0);
    // 5. h = LN2(x1)
    ln_kernel<<<TOK, 256>>>(px1, ln2_g, ln2_b, ph);
    // 6. mlp = gelu(h @ w1^T + b1)
    gemm_mma<<<dim3(MLPD / 128, TOK / 128), 256, GEMM_SMEM>>>(
        ph, w1, b1, nullptr, pmlp, TOK, MLPD, E, 1);
    // 7. out = x1 + mlp @ w2^T + b2
    gemm_mma<<<dim3(E / 128, TOK / 128), 256, GEMM_SMEM>>>(
        pmlp, w2, b2, px1, out, TOK, E, MLPD, 0);
}

// round 5
// speedup vs baseline: 4.2403x; 3.7916x over previous
#include <cuda_runtime.h>
#include <cuda_bf16.h>
#include <cstdint>
#include <math.h>

#define TOK   8192
#define E     1024
#define H3    3072
#define MLPD  4096
#define NHEAD 16
#define HDIM  64
#define SEQ   2048

// ---------------------------------------------------------------------------
// Scratch
// ---------------------------------------------------------------------------
__device__ float g_h   [(size_t)TOK * E];
__device__ float g_qkv [(size_t)TOK * H3];
__device__ float g_attn[(size_t)TOK * E];
__device__ float g_x1  [(size_t)TOK * E];
__device__ float g_mlp [(size_t)TOK * MLPD];

__device__ __forceinline__ uint32_t smem_u32(const void* p) {
    uint32_t a;
    asm("{ .reg .u64 t; cvta.to.shared.u64 t, %1; cvt.u32.u64 %0, t; }"
        : "=r"(a) : "l"(p));
    return a;
}

#define LDSM_X4(r, addr) \
    asm volatile("ldmatrix.sync.aligned.m8n8.x4.shared.b16 {%0,%1,%2,%3}, [%4];" \
        : "=r"((r)[0]), "=r"((r)[1]), "=r"((r)[2]), "=r"((r)[3]) : "r"(addr))

#define LDSM_X4_T(r, addr) \
    asm volatile("ldmatrix.sync.aligned.m8n8.x4.trans.shared.b16 {%0,%1,%2,%3}, [%4];" \
        : "=r"((r)[0]), "=r"((r)[1]), "=r"((r)[2]), "=r"((r)[3]) : "r"(addr))

__device__ __forceinline__ void mma_bf16(float* c, const uint32_t* a, const uint32_t* b) {
    asm volatile(
        "mma.sync.aligned.m16n8k16.row.col.f32.bf16.bf16.f32 "
        "{%0,%1,%2,%3}, {%4,%5,%6,%7}, {%8,%9}, {%0,%1,%2,%3};"
        : "+f"(c[0]), "+f"(c[1]), "+f"(c[2]), "+f"(c[3])
        : "r"(a[0]), "r"(a[1]), "r"(a[2]), "r"(a[3]), "r"(b[0]), "r"(b[1]));
}

// split fp32 pair into packed bf16 hi + lo parts
__device__ __forceinline__ void split_pack(float c0, float c1,
                                           uint32_t& hi, uint32_t& lo)
{
    uint32_t u0 = __float_as_uint(c0), u1 = __float_as_uint(c1);
    hi = (u1 & 0xffff0000u) | (u0 >> 16);
    float l0 = c0 - __uint_as_float(u0 & 0xffff0000u);
    float l1 = c1 - __uint_as_float(u1 & 0xffff0000u);
    asm("cvt.rn.bf16x2.f32 %0, %1, %2;" : "=r"(lo) : "f"(l1), "f"(l0));
}

// ---------------------------------------------------------------------------
// LayerNorm
// ---------------------------------------------------------------------------
__global__ void ln_kernel(const float* __restrict__ x,
                          const float* __restrict__ g,
                          const float* __restrict__ b,
                          float* __restrict__ y)
{
    int row = blockIdx.x;
    int tid = threadIdx.x;
    const float4* xr = (const float4*)(x + (size_t)row * E);
    float4 v = xr[tid];

    float s  = v.x + v.y + v.z + v.w;
    float ss = v.x * v.x + v.y * v.y + v.z * v.z + v.w * v.w;

    __shared__ float sbuf[32], sbuf2[32];
    #pragma unroll
    for (int o = 16; o > 0; o >>= 1) {
        s  += __shfl_down_sync(0xffffffffu, s,  o);
        ss += __shfl_down_sync(0xffffffffu, ss, o);
    }
    int warp = tid >> 5, lane = tid & 31;
    if (lane == 0) { sbuf[warp] = s; sbuf2[warp] = ss; }
    __syncthreads();
    if (warp == 0) {
        s  = lane < 8 ? sbuf[lane]  : 0.f;
        ss = lane < 8 ? sbuf2[lane] : 0.f;
        #pragma unroll
        for (int o = 4; o > 0; o >>= 1) {
            s  += __shfl_down_sync(0xffffffffu, s,  o);
            ss += __shfl_down_sync(0xffffffffu, ss, o);
        }
        if (lane == 0) { sbuf[0] = s; sbuf2[0] = ss; }
    }
    __syncthreads();
    float mean = sbuf[0] * (1.0f / E);
    float var  = sbuf2[0] * (1.0f / E) - mean * mean;
    float rstd = rsqrtf(var + 1e-5f);

    float4 gv = ((const float4*)g)[tid];
    float4 bv = ((const float4*)b)[tid];
    float4 o;
    o.x = (v.x - mean) * rstd * gv.x + bv.x;
    o.y = (v.y - mean) * rstd * gv.y + bv.y;
    o.z = (v.z - mean) * rstd * gv.z + bv.z;
    o.w = (v.w - mean) * rstd * gv.w + bv.w;
    ((float4*)(y + (size_t)row * E))[tid] = o;
}

// ---------------------------------------------------------------------------
// Split-bf16 mma.sync NT GEMM (unchanged from R3)
// ---------------------------------------------------------------------------
#define SROW   80
#define MATB   10240
#define STAGEB 40960
#define GEMM_SMEM (2 * STAGEB)

struct StageRegs { float4 a[4]; float4 b[4]; };

__device__ __forceinline__ void ldg_stage(StageRegs& s,
                                          const float* __restrict__ Ab,
                                          const float* __restrict__ Bb,
                                          int K, int k0, int tid)
{
    #pragma unroll
    for (int i = 0; i < 4; i++) {
        int idx = i * 256 + tid;
        int r = idx >> 3, c4 = idx & 7;
        s.a[i] = *(const float4*)(Ab + (size_t)r * K + k0 + c4 * 4);
        s.b[i] = *(const float4*)(Bb + (size_t)r * K + k0 + c4 * 4);
    }
}

__device__ __forceinline__ void cvt_sts(float4 v, char* hi, char* lo, uint32_t off)
{
    uint32_t x0 = __float_as_uint(v.x), x1 = __float_as_uint(v.y);
    uint32_t x2 = __float_as_uint(v.z), x3 = __float_as_uint(v.w);
    uint32_t h01 = (x1 & 0xffff0000u) | (x0 >> 16);
    uint32_t h23 = (x3 & 0xffff0000u) | (x2 >> 16);
    float l0 = v.x - __uint_as_float(x0 & 0xffff0000u);
    float l1 = v.y - __uint_as_float(x1 & 0xffff0000u);
    float l2 = v.z - __uint_as_float(x2 & 0xffff0000u);
    float l3 = v.w - __uint_as_float(x3 & 0xffff0000u);
    uint32_t l01, l23;
    asm("cvt.rn.bf16x2.f32 %0, %1, %2;" : "=r"(l01) : "f"(l1), "f"(l0));
    asm("cvt.rn.bf16x2.f32 %0, %1, %2;" : "=r"(l23) : "f"(l3), "f"(l2));
    *(uint2*)(hi + off) = make_uint2(h01, h23);
    *(uint2*)(lo + off) = make_uint2(l01, l23);
}

__device__ __forceinline__ void sts_stage(const StageRegs& s, char* stg, int tid)
{
    #pragma unroll
    for (int i = 0; i < 4; i++) {
        int idx = i * 256 + tid;
        int r = idx >> 3, c4 = idx & 7;
        uint32_t off = (uint32_t)(r * SROW + c4 * 8);
        cvt_sts(s.a[i], stg,            stg + MATB,     off);
        cvt_sts(s.b[i], stg + 2 * MATB, stg + 3 * MATB, off);
    }
}

__global__ __launch_bounds__(256, 1)
void gemm_mma(const float* __restrict__ A, const float* __restrict__ B,
              const float* __restrict__ bias, const float* __restrict__ res,
              float* __restrict__ C, int M, int N, int K, int act)
{
    extern __shared__ char sm[];
    uint32_t sb = smem_u32(sm);
    int tid = threadIdx.x, w = tid >> 5, lane = tid & 31;
    int wm = w >> 2, wn = w & 3;
    int bn = blockIdx.x, bm = blockIdx.y;

    const float* Ab = A + (size_t)bm * 128 * K;
    const float* Bb = B + (size_t)bn * 128 * K;
    int nch = K >> 5;

    float acc[4][4][4];
    #pragma unroll
    for (int i = 0; i < 4; i++)
        #pragma unroll
        for (int j = 0; j < 4; j++)
            #pragma unroll
            for (int c = 0; c < 4; c++) acc[i][j][c] = 0.f;

    StageRegs st;
    ldg_stage(st, Ab, Bb, K, 0, tid);
    sts_stage(st, sm, tid);
    __syncthreads();

    uint32_t a_row = (uint32_t)(wm * 64 + (lane & 15)) * SROW + ((lane >> 4) * 8) * 2;
    uint32_t b_row = (uint32_t)(wn * 32 + (lane & 7) + ((lane >> 4) & 1) * 8) * SROW
                   + (((lane >> 3) & 1) * 8) * 2;

    for (int k = 0; k < nch; k++) {
        StageRegs nxt;
        if (k + 1 < nch) ldg_stage(nxt, Ab, Bb, K, (k + 1) * 32, tid);

        uint32_t stg = sb + (uint32_t)(k & 1) * STAGEB;
        #pragma unroll
        for (int ks = 0; ks < 2; ks++) {
            uint32_t koff = (uint32_t)(ks * 32);
            uint32_t ah[4][4], al[4][4], bh[2][4], bl[2][4];
            #pragma unroll
            for (int mf = 0; mf < 4; mf++) {
                uint32_t addr = stg + a_row + (uint32_t)(mf * 16) * SROW + koff;
                LDSM_X4(ah[mf], addr);
                LDSM_X4(al[mf], addr + MATB);
            }
            #pragma unroll
            for (int np = 0; np < 2; np++) {
                uint32_t addr = stg + 2 * MATB + b_row + (uint32_t)(np * 16) * SROW + koff;
                LDSM_X4(bh[np], addr);
                LDSM_X4(bl[np], addr + MATB);
            }
            #pragma unroll
            for (int mf = 0; mf < 4; mf++)
                #pragma unroll
                for (int nf = 0; nf < 4; nf++) {
                    const uint32_t* bhf = &bh[nf >> 1][(nf & 1) * 2];
                    const uint32_t* blf = &bl[nf >> 1][(nf & 1) * 2];
                    mma_bf16(acc[mf][nf], ah[mf], bhf);
                    mma_bf16(acc[mf][nf], ah[mf], blf);
                    mma_bf16(acc[mf][nf], al[mf], bhf);
                }
        }
        __syncthreads();
        if (k + 1 < nch) {
            sts_stage(nxt, sm + ((k + 1) & 1) * STAGEB, tid);
            __syncthreads();
        }
    }

    int g = lane >> 2, tig = lane & 3;
    #pragma unroll
    for (int mf = 0; mf < 4; mf++) {
        #pragma unroll
        for (int h2 = 0; h2 < 2; h2++) {
            int row = bm * 128 + wm * 64 + mf * 16 + g + h2 * 8;
            float* Crow = C + (size_t)row * N;
            const float* Rrow = res ? res + (size_t)row * N : (const float*)0;
            #pragma unroll
            for (int nf = 0; nf < 4; nf++) {
                int col = bn * 128 + wn * 32 + nf * 8 + tig * 2;
                float v0 = acc[mf][nf][h2 * 2 + 0];
                float v1 = acc[mf][nf][h2 * 2 + 1];
                if (bias) {
                    float2 bv = *(const float2*)(bias + col);
                    v0 += bv.x; v1 += bv.y;
                }
                if (act == 1) {
                    v0 = 0.5f * v0 * (1.0f + erff(v0 * 0.70710678118654752f));
                    v1 = 0.5f * v1 * (1.0f + erff(v1 * 0.70710678118654752f));
                }
                if (Rrow) {
                    float2 rv = *(const float2*)(Rrow + col);
                    v0 += rv.x; v1 += rv.y;
                }
                *(float2*)(Crow + col) = make_float2(v0, v1);
            }
        }
    }
}

// ---------------------------------------------------------------------------
// Tensor-core flash attention.
// CTA: 128 Q rows x one (head, batch). 4 warps, each 32 rows. KV tiles: 64.
// Q/K/V in smem as split bf16 hi/lo, row stride 144 B (72 bf16).
// ---------------------------------------------------------------------------
#define AROW 144
#define Q_HI 0
#define Q_LO 18432              // 128*144
#define K_HI 36864
#define K_LO 46080              // +64*144
#define V_HI 55296
#define V_LO 64512
#define ATTN_SMEM 73728

__global__ __launch_bounds__(128)
void attn_mma(const float* __restrict__ qkv, float* __restrict__ out)
{
    extern __shared__ char sm[];
    uint32_t sb = smem_u32(sm);
    int qt = blockIdx.x, h = blockIdx.y, b = blockIdx.z;
    int tid = threadIdx.x, w = tid >> 5, lane = tid & 31;
    int g = lane >> 2, tig = lane & 3;

    // load Q tile (scaled by 1/8), split hi/lo
    #pragma unroll
    for (int i = 0; i < 16; i++) {
        int idx = i * 128 + tid;
        int r = idx >> 4, c4 = idx & 15;
        size_t token = (size_t)(b * SEQ + qt * 128 + r);
        float4 v = *(const float4*)(qkv + token * H3 + h * HDIM + c4 * 4);
        v.x *= 0.125f; v.y *= 0.125f; v.z *= 0.125f; v.w *= 0.125f;
        cvt_sts(v, sm + Q_HI, sm + Q_LO, (uint32_t)(r * AROW + c4 * 8));
    }

    float o[2][8][4];
    #pragma unroll
    for (int mf = 0; mf < 2; mf++)
        #pragma unroll
        for (int nf = 0; nf < 8; nf++)
            #pragma unroll
            for (int c = 0; c < 4; c++) o[mf][nf][c] = 0.f;
    float m_[2][2] = {{-1e30f, -1e30f}, {-1e30f, -1e30f}};
    float l_[2][2] = {{0.f, 0.f}, {0.f, 0.f}};

    uint32_t qa_base = sb + Q_HI + (uint32_t)(w * 32 + (lane & 15)) * AROW
                     + ((lane >> 4) * 8) * 2;
    uint32_t kb_base = sb + K_HI
                     + (uint32_t)((lane & 7) + ((lane >> 4) & 1) * 8) * AROW
                     + (((lane >> 3) & 1) * 8) * 2;
    uint32_t vb_base = sb + V_HI + (uint32_t)(lane & 15) * AROW
                     + ((lane >> 4) * 8) * 2;

    for (int kt = 0; kt < SEQ / 64; kt++) {
        __syncthreads();
        // load K, V tiles (64 x 64) -> split smem
        #pragma unroll
        for (int i = 0; i < 8; i++) {
            int idx = i * 128 + tid;
            int r = idx >> 4, c4 = idx & 15;
            size_t base = (size_t)(b * SEQ + kt * 64 + r) * H3 + h * HDIM + c4 * 4;
            float4 kv = *(const float4*)(qkv + base + E);
            float4 vv = *(const float4*)(qkv + base + 2 * E);
            uint32_t off = (uint32_t)(r * AROW + c4 * 8);
            cvt_sts(kv, sm + K_HI, sm + K_LO, off);
            cvt_sts(vv, sm + V_HI, sm + V_LO, off);
        }
        __syncthreads();

        // ---- S = Q K^T ----
        float s[2][8][4];
        #pragma unroll
        for (int mf = 0; mf < 2; mf++)
            #pragma unroll
            for (int nf = 0; nf < 8; nf++)
                #pragma unroll
                for (int c = 0; c < 4; c++) s[mf][nf][c] = 0.f;

        #pragma unroll
        for (int ks = 0; ks < 4; ks++) {
            uint32_t koff = (uint32_t)(ks * 32);
            uint32_t qh[2][4], ql[2][4], kh[4][4], kl[4][4];
            #pragma unroll
            for (int mf = 0; mf < 2; mf++) {
                uint32_t addr = qa_base + (uint32_t)(mf * 16) * AROW + koff;
                LDSM_X4(qh[mf], addr);
                LDSM_X4(ql[mf], addr + (Q_LO - Q_HI));
            }
            #pragma unroll
            for (int ng = 0; ng < 4; ng++) {
                uint32_t addr = kb_base + (uint32_t)(ng * 16) * AROW + koff;
                LDSM_X4(kh[ng], addr);
                LDSM_X4(kl[ng], addr + (K_LO - K_HI));
            }
            #pragma unroll
            for (int mf = 0; mf < 2; mf++)
                #pragma unroll
                for (int nf = 0; nf < 8; nf++) {
                    const uint32_t* bh = &kh[nf >> 1][(nf & 1) * 2];
                    const uint32_t* bl = &kl[nf >> 1][(nf & 1) * 2];
                    mma_bf16(s[mf][nf], qh[mf], bh);
                    mma_bf16(s[mf][nf], qh[mf], bl);
                    mma_bf16(s[mf][nf], ql[mf], bh);
                }
        }

        // ---- online softmax (per row, quad-reduced) ----
        #pragma unroll
        for (int mf = 0; mf < 2; mf++)
            #pragma unroll
            for (int hh = 0; hh < 2; hh++) {
                float mx = s[mf][0][hh * 2];
                #pragma unroll
                for (int nf = 0; nf < 8; nf++) {
                    mx = fmaxf(mx, s[mf][nf][hh * 2 + 0]);
                    mx = fmaxf(mx, s[mf][nf][hh * 2 + 1]);
                }
                mx = fmaxf(mx, __shfl_xor_sync(0xffffffffu, mx, 1));
                mx = fmaxf(mx, __shfl_xor_sync(0xffffffffu, mx, 2));
                float mn = fmaxf(m_[mf][hh], mx);
                float alpha = __expf(m_[mf][hh] - mn);
                m_[mf][hh] = mn;
                float lsum = 0.f;
                #pragma unroll
                for (int nf = 0; nf < 8; nf++) {
                    float p0 = __expf(s[mf][nf][hh * 2 + 0] - mn);
                    float p1 = __expf(s[mf][nf][hh * 2 + 1] - mn);
                    s[mf][nf][hh * 2 + 0] = p0;
                    s[mf][nf][hh * 2 + 1] = p1;
                    lsum += p0 + p1;
                    o[mf][nf][hh * 2 + 0] *= alpha;
                    o[mf][nf][hh * 2 + 1] *= alpha;
                }
                l_[mf][hh] = l_[mf][hh] * alpha + lsum;
            }

        // ---- O += P V ----
        #pragma unroll
        for (int ks = 0; ks < 4; ks++) {
            uint32_t ph[2][4], pl[2][4];
            #pragma unroll
            for (int mf = 0; mf < 2; mf++) {
                split_pack(s[mf][ks*2  ][0], s[mf][ks*2  ][1], ph[mf][0], pl[mf][0]);
                split_pack(s[mf][ks*2  ][2], s[mf][ks*2  ][3], ph[mf][1], pl[mf][1]);
                split_pack(s[mf][ks*2+1][0], s[mf][ks*2+1][1], ph[mf][2], pl[mf][2]);
                split_pack(s[mf][ks*2+1][2], s[mf][ks*2+1][3], ph[mf][3], pl[mf][3]);
            }
            uint32_t vh[4][4], vl[4][4];
            #pragma unroll
            for (int nd = 0; nd < 4; nd++) {
                uint32_t addr = vb_base + (uint32_t)(ks * 16) * AROW
                              + (uint32_t)(nd * 16) * 2;
                LDSM_X4_T(vh[nd], addr);
                LDSM_X4_T(vl[nd], addr + (V_LO - V_HI));
            }
            #pragma unroll
            for (int mf = 0; mf < 2; mf++)
                #pragma unroll
                for (int nf = 0; nf < 8; nf++) {
                    const uint32_t* bh = &vh[nf >> 1][(nf & 1) * 2];
                    const uint32_t* bl = &vl[nf >> 1][(nf & 1) * 2];
                    mma_bf16(o[mf][nf], ph[mf], bh);
                    mma_bf16(o[mf][nf], ph[mf], bl);
                    mma_bf16(o[mf][nf], pl[mf], bh);
                }
        }
    }

    // ---- finalize ----
    #pragma unroll
    for (int mf = 0; mf < 2; mf++)
        #pragma unroll
        for (int hh = 0; hh < 2; hh++) {
            float lt = l_[mf][hh];
            lt += __shfl_xor_sync(0xffffffffu, lt, 1);
            lt += __shfl_xor_sync(0xffffffffu, lt, 2);
            float inv = 1.0f / lt;
            int row = qt * 128 + w * 32 + mf * 16 + g + hh * 8;
            size_t token = (size_t)(b * SEQ + row);
            float* op = out + token * E + h * HDIM;
            #pragma unroll
            for (int nf = 0; nf < 8; nf++) {
                int col = nf * 8 + tig * 2;
                *(float2*)(op + col) = make_float2(o[mf][nf][hh * 2 + 0] * inv,
                                                   o[mf][nf][hh * 2 + 1] * inv);
            }
        }
}

// ---------------------------------------------------------------------------
// Launch
// ---------------------------------------------------------------------------
extern "C" void kernel_launch(void* const* d_in, const int* in_sizes, int n_in,
                              void* d_out, int out_size)
{
    const float* x     = (const float*)d_in[0];
    const float* qkv_w = (const float*)d_in[1];
    const float* fc_w  = (const float*)d_in[2];
    const float* fc_b  = (const float*)d_in[3];
    const float* ln1_g = (const float*)d_in[4];
    const float* ln1_b = (const float*)d_in[5];
    const float* ln2_g = (const float*)d_in[6];
    const float* ln2_b = (const float*)d_in[7];
    const float* w1    = (const float*)d_in[8];
    const float* b1    = (const float*)d_in[9];
    const float* w2    = (const float*)d_in[10];
    const float* b2    = (const float*)d_in[11];
    float* out = (float*)d_out;

    float *ph, *pqkv, *pattn, *px1, *pmlp;
    cudaGetSymbolAddress((void**)&ph,    g_h);
    cudaGetSymbolAddress((void**)&pqkv,  g_qkv);
    cudaGetSymbolAddress((void**)&pattn, g_attn);
    cudaGetSymbolAddress((void**)&px1,   g_x1);
    cudaGetSymbolAddress((void**)&pmlp,  g_mlp);

    cudaFuncSetAttribute(gemm_mma, cudaFuncAttributeMaxDynamicSharedMemorySize,
                         GEMM_SMEM);
    cudaFuncSetAttribute(attn_mma, cudaFuncAttributeMaxDynamicSharedMemorySize,
                         ATTN_SMEM);

    ln_kernel<<<TOK, 256>>>(x, ln1_g, ln1_b, ph);
    gemm_mma<<<dim3(H3 / 128, TOK / 128), 256, GEMM_SMEM>>>(
        ph, qkv_w, nullptr, nullptr, pqkv, TOK, H3, E, 0);
    attn_mma<<<dim3(SEQ / 128, NHEAD, 4), 128, ATTN_SMEM>>>(pqkv, pattn);
    gemm_mma<<<dim3(E / 128, TOK / 128), 256, GEMM_SMEM>>>(
        pattn, fc_w, fc_b, x, px1, TOK, E, E, 0);
    ln_kernel<<<TOK, 256>>>(px1, ln2_g, ln2_b, ph);
    gemm_mma<<<dim3(MLPD / 128, TOK / 128), 256, GEMM_SMEM>>>(
        ph, w1, b1, nullptr, pmlp, TOK, MLPD, E, 1);
    gemm_mma<<<dim3(E / 128, TOK / 128), 256, GEMM_SMEM>>>(
        pmlp, w2, b2, px1, out, TOK, E, MLPD, 0);
}

// round 6
// speedup vs baseline: 4.2832x; 1.0101x over previous
#include <cuda_runtime.h>
#include <cuda_bf16.h>
#include <cstdint>
#include <math.h>

#define TOK   8192
#define E     1024
#define H3    3072
#define MLPD  4096
#define NHEAD 16
#define HDIM  64
#define SEQ   2048

// ---------------------------------------------------------------------------
// Scratch
// ---------------------------------------------------------------------------
__device__ float g_h   [(size_t)TOK * E];
__device__ float g_qkv [(size_t)TOK * H3];
__device__ float g_attn[(size_t)TOK * E];
__device__ float g_x1  [(size_t)TOK * E];
__device__ float g_mlp [(size_t)TOK * MLPD];

__device__ __forceinline__ uint32_t smem_u32(const void* p) {
    uint32_t a;
    asm("{ .reg .u64 t; cvta.to.shared.u64 t, %1; cvt.u32.u64 %0, t; }"
        : "=r"(a) : "l"(p));
    return a;
}

#define LDSM_X4(r, addr) \
    asm volatile("ldmatrix.sync.aligned.m8n8.x4.shared.b16 {%0,%1,%2,%3}, [%4];" \
        : "=r"((r)[0]), "=r"((r)[1]), "=r"((r)[2]), "=r"((r)[3]) : "r"(addr))

#define LDSM_X4_T(r, addr) \
    asm volatile("ldmatrix.sync.aligned.m8n8.x4.trans.shared.b16 {%0,%1,%2,%3}, [%4];" \
        : "=r"((r)[0]), "=r"((r)[1]), "=r"((r)[2]), "=r"((r)[3]) : "r"(addr))

__device__ __forceinline__ void mma_bf16(float* c, const uint32_t* a, const uint32_t* b) {
    asm volatile(
        "mma.sync.aligned.m16n8k16.row.col.f32.bf16.bf16.f32 "
        "{%0,%1,%2,%3}, {%4,%5,%6,%7}, {%8,%9}, {%0,%1,%2,%3};"
        : "+f"(c[0]), "+f"(c[1]), "+f"(c[2]), "+f"(c[3])
        : "r"(a[0]), "r"(a[1]), "r"(a[2]), "r"(a[3]), "r"(b[0]), "r"(b[1]));
}

__device__ __forceinline__ void split_pack(float c0, float c1,
                                           uint32_t& hi, uint32_t& lo)
{
    uint32_t u0 = __float_as_uint(c0), u1 = __float_as_uint(c1);
    hi = (u1 & 0xffff0000u) | (u0 >> 16);
    float l0 = c0 - __uint_as_float(u0 & 0xffff0000u);
    float l1 = c1 - __uint_as_float(u1 & 0xffff0000u);
    asm("cvt.rn.bf16x2.f32 %0, %1, %2;" : "=r"(lo) : "f"(l1), "f"(l0));
}

__device__ __forceinline__ float ex2(float x) {
    float r;
    asm("ex2.approx.f32 %0, %1;" : "=f"(r) : "f"(x));
    return r;
}

// ---------------------------------------------------------------------------
// LayerNorm
// ---------------------------------------------------------------------------
__global__ void ln_kernel(const float* __restrict__ x,
                          const float* __restrict__ g,
                          const float* __restrict__ b,
                          float* __restrict__ y)
{
    int row = blockIdx.x;
    int tid = threadIdx.x;
    const float4* xr = (const float4*)(x + (size_t)row * E);
    float4 v = xr[tid];

    float s  = v.x + v.y + v.z + v.w;
    float ss = v.x * v.x + v.y * v.y + v.z * v.z + v.w * v.w;

    __shared__ float sbuf[32], sbuf2[32];
    #pragma unroll
    for (int o = 16; o > 0; o >>= 1) {
        s  += __shfl_down_sync(0xffffffffu, s,  o);
        ss += __shfl_down_sync(0xffffffffu, ss, o);
    }
    int warp = tid >> 5, lane = tid & 31;
    if (lane == 0) { sbuf[warp] = s; sbuf2[warp] = ss; }
    __syncthreads();
    if (warp == 0) {
        s  = lane < 8 ? sbuf[lane]  : 0.f;
        ss = lane < 8 ? sbuf2[lane] : 0.f;
        #pragma unroll
        for (int o = 4; o > 0; o >>= 1) {
            s  += __shfl_down_sync(0xffffffffu, s,  o);
            ss += __shfl_down_sync(0xffffffffu, ss, o);
        }
        if (lane == 0) { sbuf[0] = s; sbuf2[0] = ss; }
    }
    __syncthreads();
    float mean = sbuf[0] * (1.0f / E);
    float var  = sbuf2[0] * (1.0f / E) - mean * mean;
    float rstd = rsqrtf(var + 1e-5f);

    float4 gv = ((const float4*)g)[tid];
    float4 bv = ((const float4*)b)[tid];
    float4 o;
    o.x = (v.x - mean) * rstd * gv.x + bv.x;
    o.y = (v.y - mean) * rstd * gv.y + bv.y;
    o.z = (v.z - mean) * rstd * gv.z + bv.z;
    o.w = (v.w - mean) * rstd * gv.w + bv.w;
    ((float4*)(y + (size_t)row * E))[tid] = o;
}

// ---------------------------------------------------------------------------
// Split-bf16 mma.sync NT GEMM (R3 proven; redundant barrier removed)
// ---------------------------------------------------------------------------
#define SROW   80
#define MATB   10240
#define STAGEB 40960
#define GEMM_SMEM (2 * STAGEB)

struct StageRegs { float4 a[4]; float4 b[4]; };

__device__ __forceinline__ void ldg_stage(StageRegs& s,
                                          const float* __restrict__ Ab,
                                          const float* __restrict__ Bb,
                                          int K, int k0, int tid)
{
    #pragma unroll
    for (int i = 0; i < 4; i++) {
        int idx = i * 256 + tid;
        int r = idx >> 3, c4 = idx & 7;
        s.a[i] = *(const float4*)(Ab + (size_t)r * K + k0 + c4 * 4);
        s.b[i] = *(const float4*)(Bb + (size_t)r * K + k0 + c4 * 4);
    }
}

__device__ __forceinline__ void cvt_sts(float4 v, char* hi, char* lo, uint32_t off)
{
    uint32_t x0 = __float_as_uint(v.x), x1 = __float_as_uint(v.y);
    uint32_t x2 = __float_as_uint(v.z), x3 = __float_as_uint(v.w);
    uint32_t h01 = (x1 & 0xffff0000u) | (x0 >> 16);
    uint32_t h23 = (x3 & 0xffff0000u) | (x2 >> 16);
    float l0 = v.x - __uint_as_float(x0 & 0xffff0000u);
    float l1 = v.y - __uint_as_float(x1 & 0xffff0000u);
    float l2 = v.z - __uint_as_float(x2 & 0xffff0000u);
    float l3 = v.w - __uint_as_float(x3 & 0xffff0000u);
    uint32_t l01, l23;
    asm("cvt.rn.bf16x2.f32 %0, %1, %2;" : "=r"(l01) : "f"(l1), "f"(l0));
    asm("cvt.rn.bf16x2.f32 %0, %1, %2;" : "=r"(l23) : "f"(l3), "f"(l2));
    *(uint2*)(hi + off) = make_uint2(h01, h23);
    *(uint2*)(lo + off) = make_uint2(l01, l23);
}

__device__ __forceinline__ void sts_stage(const StageRegs& s, char* stg, int tid)
{
    #pragma unroll
    for (int i = 0; i < 4; i++) {
        int idx = i * 256 + tid;
        int r = idx >> 3, c4 = idx & 7;
        uint32_t off = (uint32_t)(r * SROW + c4 * 8);
        cvt_sts(s.a[i], stg,            stg + MATB,     off);
        cvt_sts(s.b[i], stg + 2 * MATB, stg + 3 * MATB, off);
    }
}

__global__ __launch_bounds__(256, 1)
void gemm_mma(const float* __restrict__ A, const float* __restrict__ B,
              const float* __restrict__ bias, const float* __restrict__ res,
              float* __restrict__ C, int M, int N, int K, int act)
{
    extern __shared__ char sm[];
    uint32_t sb = smem_u32(sm);
    int tid = threadIdx.x, w = tid >> 5, lane = tid & 31;
    int wm = w >> 2, wn = w & 3;
    int bn = blockIdx.x, bm = blockIdx.y;

    const float* Ab = A + (size_t)bm * 128 * K;
    const float* Bb = B + (size_t)bn * 128 * K;
    int nch = K >> 5;

    float acc[4][4][4];
    #pragma unroll
    for (int i = 0; i < 4; i++)
        #pragma unroll
        for (int j = 0; j < 4; j++)
            #pragma unroll
            for (int c = 0; c < 4; c++) acc[i][j][c] = 0.f;

    StageRegs st;
    ldg_stage(st, Ab, Bb, K, 0, tid);
    sts_stage(st, sm, tid);
    __syncthreads();

    uint32_t a_row = (uint32_t)(wm * 64 + (lane & 15)) * SROW + ((lane >> 4) * 8) * 2;
    uint32_t b_row = (uint32_t)(wn * 32 + (lane & 7) + ((lane >> 4) & 1) * 8) * SROW
                   + (((lane >> 3) & 1) * 8) * 2;

    for (int k = 0; k < nch; k++) {
        StageRegs nxt;
        if (k + 1 < nch) ldg_stage(nxt, Ab, Bb, K, (k + 1) * 32, tid);

        uint32_t stg = sb + (uint32_t)(k & 1) * STAGEB;
        #pragma unroll
        for (int ks = 0; ks < 2; ks++) {
            uint32_t koff = (uint32_t)(ks * 32);
            uint32_t ah[4][4], al[4][4], bh[2][4], bl[2][4];
            #pragma unroll
            for (int mf = 0; mf < 4; mf++) {
                uint32_t addr = stg + a_row + (uint32_t)(mf * 16) * SROW + koff;
                LDSM_X4(ah[mf], addr);
                LDSM_X4(al[mf], addr + MATB);
            }
            #pragma unroll
            for (int np = 0; np < 2; np++) {
                uint32_t addr = stg + 2 * MATB + b_row + (uint32_t)(np * 16) * SROW + koff;
                LDSM_X4(bh[np], addr);
                LDSM_X4(bl[np], addr + MATB);
            }
            #pragma unroll
            for (int mf = 0; mf < 4; mf++)
                #pragma unroll
                for (int nf = 0; nf < 4; nf++) {
                    const uint32_t* bhf = &bh[nf >> 1][(nf & 1) * 2];
                    const uint32_t* blf = &bl[nf >> 1][(nf & 1) * 2];
                    mma_bf16(acc[mf][nf], ah[mf], bhf);
                    mma_bf16(acc[mf][nf], ah[mf], blf);
                    mma_bf16(acc[mf][nf], al[mf], bhf);
                }
        }
        if (k + 1 < nch) sts_stage(nxt, sm + ((k + 1) & 1) * STAGEB, tid);
        __syncthreads();
    }

    int g = lane >> 2, tig = lane & 3;
    #pragma unroll
    for (int mf = 0; mf < 4; mf++) {
        #pragma unroll
        for (int h2 = 0; h2 < 2; h2++) {
            int row = bm * 128 + wm * 64 + mf * 16 + g + h2 * 8;
            float* Crow = C + (size_t)row * N;
            const float* Rrow = res ? res + (size_t)row * N : (const float*)0;
            #pragma unroll
            for (int nf = 0; nf < 4; nf++) {
                int col = bn * 128 + wn * 32 + nf * 8 + tig * 2;
                float v0 = acc[mf][nf][h2 * 2 + 0];
                float v1 = acc[mf][nf][h2 * 2 + 1];
                if (bias) {
                    float2 bv = *(const float2*)(bias + col);
                    v0 += bv.x; v1 += bv.y;
                }
                if (act == 1) {
                    v0 = 0.5f * v0 * (1.0f + erff(v0 * 0.70710678118654752f));
                    v1 = 0.5f * v1 * (1.0f + erff(v1 * 0.70710678118654752f));
                }
                if (Rrow) {
                    float2 rv = *(const float2*)(Rrow + col);
                    v0 += rv.x; v1 += rv.y;
                }
                *(float2*)(Crow + col) = make_float2(v0, v1);
            }
        }
    }
}

// ---------------------------------------------------------------------------
// Tensor-core flash attention v2.
// CTA: 128 Q rows x (head, batch). 256 threads / 8 warps, each warp 16 rows.
// KV tiles of 64 keys, double-buffered. Q fragments preloaded in registers.
// Softmax in base-2 (log2e folded into Q scale).
// ---------------------------------------------------------------------------
#define AROW 144
#define Q_HI 0
#define Q_LO 18432
#define KV0  36864
#define KVSTG 36864     // per stage: K_HI+0, K_LO+9216, V_HI+18432, V_LO+27648
#define ATTN_SMEM (KV0 + 2 * KVSTG)
#define QSCALE 0.18033688011112042f   // 0.125 * log2(e)

struct KVregs { float4 k[4]; float4 v[4]; };

__device__ __forceinline__ void ldg_kv(KVregs& r, const float* __restrict__ qkv,
                                       int b, int h, int kt, int tid)
{
    #pragma unroll
    for (int i = 0; i < 4; i++) {
        int idx = i * 256 + tid;
        int rr = idx >> 4, c4 = idx & 15;
        size_t base = (size_t)(b * SEQ + kt * 64 + rr) * H3 + h * HDIM + c4 * 4;
        r.k[i] = *(const float4*)(qkv + base + E);
        r.v[i] = *(const float4*)(qkv + base + 2 * E);
    }
}

__device__ __forceinline__ void sts_kv(const KVregs& r, char* stg, int tid)
{
    #pragma unroll
    for (int i = 0; i < 4; i++) {
        int idx = i * 256 + tid;
        int rr = idx >> 4, c4 = idx & 15;
        uint32_t off = (uint32_t)(rr * AROW + c4 * 8);
        cvt_sts(r.k[i], stg,         stg + 9216,  off);
        cvt_sts(r.v[i], stg + 18432, stg + 27648, off);
    }
}

__global__ __launch_bounds__(256)
void attn_mma(const float* __restrict__ qkv, float* __restrict__ out)
{
    extern __shared__ char sm[];
    uint32_t sb = smem_u32(sm);
    int qt = blockIdx.x, h = blockIdx.y, b = blockIdx.z;
    int tid = threadIdx.x, w = tid >> 5, lane = tid & 31;
    int g = lane >> 2, tig = lane & 3;

    // load Q tile (scaled), split hi/lo
    #pragma unroll
    for (int i = 0; i < 8; i++) {
        int idx = i * 256 + tid;
        int r = idx >> 4, c4 = idx & 15;
        size_t token = (size_t)(b * SEQ + qt * 128 + r);
        float4 v = *(const float4*)(qkv + token * H3 + h * HDIM + c4 * 4);
        v.x *= QSCALE; v.y *= QSCALE; v.z *= QSCALE; v.w *= QSCALE;
        cvt_sts(v, sm + Q_HI, sm + Q_LO, (uint32_t)(r * AROW + c4 * 8));
    }

    // KV tile 0
    {
        KVregs r0;
        ldg_kv(r0, qkv, b, h, 0, tid);
        sts_kv(r0, sm + KV0, tid);
    }
    __syncthreads();

    // preload Q fragments (16 rows of this warp, 4 k-steps)
    uint32_t qh[4][4], ql[4][4];
    {
        uint32_t qa = sb + Q_HI + (uint32_t)(w * 16 + (lane & 15)) * AROW
                    + ((lane >> 4) * 8) * 2;
        #pragma unroll
        for (int ks = 0; ks < 4; ks++) {
            LDSM_X4(qh[ks], qa + (uint32_t)(ks * 32));
            LDSM_X4(ql[ks], qa + (uint32_t)(ks * 32) + Q_LO);
        }
    }

    float o[8][4];
    #pragma unroll
    for (int nf = 0; nf < 8; nf++)
        #pragma unroll
        for (int c = 0; c < 4; c++) o[nf][c] = 0.f;
    float m_[2] = {-1e30f, -1e30f};
    float l_[2] = {0.f, 0.f};

    uint32_t kb_off = (uint32_t)((lane & 7) + ((lane >> 4) & 1) * 8) * AROW
                    + (((lane >> 3) & 1) * 8) * 2;
    uint32_t vb_off = (uint32_t)(lane & 15) * AROW + ((lane >> 4) * 8) * 2 + 18432;

    for (int kt = 0; kt < SEQ / 64; kt++) {
        uint32_t stg = sb + KV0 + (uint32_t)(kt & 1) * KVSTG;

        KVregs nxt;
        if (kt + 1 < SEQ / 64) ldg_kv(nxt, qkv, b, h, kt + 1, tid);

        // ---- S = Q K^T ----
        float s[8][4];
        #pragma unroll
        for (int nf = 0; nf < 8; nf++)
            #pragma unroll
            for (int c = 0; c < 4; c++) s[nf][c] = 0.f;

        #pragma unroll
        for (int ks = 0; ks < 4; ks++) {
            uint32_t koff = (uint32_t)(ks * 32);
            #pragma unroll
            for (int ng = 0; ng < 4; ng++) {
                uint32_t addr = stg + kb_off + (uint32_t)(ng * 16) * AROW + koff;
                uint32_t kh[4], kl[4];
                LDSM_X4(kh, addr);
                LDSM_X4(kl, addr + 9216);
                #pragma unroll
                for (int j = 0; j < 2; j++) {
                    int nf = ng * 2 + j;
                    mma_bf16(s[nf], qh[ks], &kh[j * 2]);
                    mma_bf16(s[nf], qh[ks], &kl[j * 2]);
                    mma_bf16(s[nf], ql[ks], &kh[j * 2]);
                }
            }
        }

        // ---- online softmax (base 2) ----
        #pragma unroll
        for (int hh = 0; hh < 2; hh++) {
            float mx = s[0][hh * 2];
            #pragma unroll
            for (int nf = 0; nf < 8; nf++) {
                mx = fmaxf(mx, s[nf][hh * 2 + 0]);
                mx = fmaxf(mx, s[nf][hh * 2 + 1]);
            }
            mx = fmaxf(mx, __shfl_xor_sync(0xffffffffu, mx, 1));
            mx = fmaxf(mx, __shfl_xor_sync(0xffffffffu, mx, 2));
            float mn = fmaxf(m_[hh], mx);
            float alpha = ex2(m_[hh] - mn);
            m_[hh] = mn;
            float lsum = 0.f;
            #pragma unroll
            for (int nf = 0; nf < 8; nf++) {
                float p0 = ex2(s[nf][hh * 2 + 0] - mn);
                float p1 = ex2(s[nf][hh * 2 + 1] - mn);
                s[nf][hh * 2 + 0] = p0;
                s[nf][hh * 2 + 1] = p1;
                lsum += p0 + p1;
                o[nf][hh * 2 + 0] *= alpha;
                o[nf][hh * 2 + 1] *= alpha;
            }
            l_[hh] = l_[hh] * alpha + lsum;
        }

        // ---- O += P V ----
        #pragma unroll
        for (int ks = 0; ks < 4; ks++) {
            uint32_t ph[4], pl[4];
            split_pack(s[ks*2  ][0], s[ks*2  ][1], ph[0], pl[0]);
            split_pack(s[ks*2  ][2], s[ks*2  ][3], ph[1], pl[1]);
            split_pack(s[ks*2+1][0], s[ks*2+1][1], ph[2], pl[2]);
            split_pack(s[ks*2+1][2], s[ks*2+1][3], ph[3], pl[3]);
            #pragma unroll
            for (int nd = 0; nd < 4; nd++) {
                uint32_t addr = stg + vb_off + (uint32_t)(ks * 16) * AROW
                              + (uint32_t)(nd * 16) * 2;
                uint32_t vh[4], vl[4];
                LDSM_X4_T(vh, addr);
                LDSM_X4_T(vl, addr + 9216);
                #pragma unroll
                for (int j = 0; j < 2; j++) {
                    int nf = nd * 2 + j;
                    mma_bf16(o[nf], ph, &vh[j * 2]);
                    mma_bf16(o[nf], ph, &vl[j * 2]);
                    mma_bf16(o[nf], pl, &vh[j * 2]);
                }
            }
        }

        if (kt + 1 < SEQ / 64)
            sts_kv(nxt, sm + KV0 + ((kt + 1) & 1) * KVSTG, tid);
        __syncthreads();
    }

    // ---- finalize ----
    #pragma unroll
    for (int hh = 0; hh < 2; hh++) {
        float lt = l_[hh];
        lt += __shfl_xor_sync(0xffffffffu, lt, 1);
        lt += __shfl_xor_sync(0xffffffffu, lt, 2);
        float inv = 1.0f / lt;
        int row = qt * 128 + w * 16 + g + hh * 8;
        size_t token = (size_t)(b * SEQ + row);
        float* op = out + token * E + h * HDIM;
        #pragma unroll
        for (int nf = 0; nf < 8; nf++) {
            int col = nf * 8 + tig * 2;
            *(float2*)(op + col) = make_float2(o[nf][hh * 2 + 0] * inv,
                                               o[nf][hh * 2 + 1] * inv);
        }
    }
}

// ---------------------------------------------------------------------------
// Launch
// ---------------------------------------------------------------------------
extern "C" void kernel_launch(void* const* d_in, const int* in_sizes, int n_in,
                              void* d_out, int out_size)
{
    const float* x     = (const float*)d_in[0];
    const float* qkv_w = (const float*)d_in[1];
    const float* fc_w  = (const float*)d_in[2];
    const float* fc_b  = (const float*)d_in[3];
    const float* ln1_g = (const float*)d_in[4];
    const float* ln1_b = (const float*)d_in[5];
    const float* ln2_g = (const float*)d_in[6];
    const float* ln2_b = (const float*)d_in[7];
    const float* w1    = (const float*)d_in[8];
    const float* b1    = (const float*)d_in[9];
    const float* w2    = (const float*)d_in[10];
    const float* b2    = (const float*)d_in[11];
    float* out = (float*)d_out;

    float *ph, *pqkv, *pattn, *px1, *pmlp;
    cudaGetSymbolAddress((void**)&ph,    g_h);
    cudaGetSymbolAddress((void**)&pqkv,  g_qkv);
    cudaGetSymbolAddress((void**)&pattn, g_attn);
    cudaGetSymbolAddress((void**)&px1,   g_x1);
    cudaGetSymbolAddress((void**)&pmlp,  g_mlp);

    cudaFuncSetAttribute(gemm_mma, cudaFuncAttributeMaxDynamicSharedMemorySize,
                         GEMM_SMEM);
    cudaFuncSetAttribute(attn_mma, cudaFuncAttributeMaxDynamicSharedMemorySize,
                         ATTN_SMEM);

    ln_kernel<<<TOK, 256>>>(x, ln1_g, ln1_b, ph);
    gemm_mma<<<dim3(H3 / 128, TOK / 128), 256, GEMM_SMEM>>>(
        ph, qkv_w, nullptr, nullptr, pqkv, TOK, H3, E, 0);
    attn_mma<<<dim3(SEQ / 128, NHEAD, 4), 256, ATTN_SMEM>>>(pqkv, pattn);
    gemm_mma<<<dim3(E / 128, TOK / 128), 256, GEMM_SMEM>>>(
        pattn, fc_w, fc_b, x, px1, TOK, E, E, 0);
    ln_kernel<<<TOK, 256>>>(px1, ln2_g, ln2_b, ph);
    gemm_mma<<<dim3(MLPD / 128, TOK / 128), 256, GEMM_SMEM>>>(
        ph, w1, b1, nullptr, pmlp, TOK, MLPD, E, 1);
    gemm_mma<<<dim3(E / 128, TOK / 128), 256, GEMM_SMEM>>>(
        pmlp, w2, b2, px1, out, TOK, E, MLPD, 0);
}